// round 7
// baseline (speedup 1.0000x reference)
#include <cuda_runtime.h>
#include <math.h>

#define N_    1024
#define H_    12
#define C1_   384
#define C2_   128
#define COUT_ 384
#define NPROJ 1152
#define NFEAT 2112
#define QB    2
#define TM    32
#define PITCH 132
#define BUFF  (QB * TM * PITCH)   // 8448 floats per buffer

#define W2DS 0.5773502691896258f
#define SCW  0.14433756729740643f
#define PTW  0.1360827634879543f

typedef unsigned long long u64;

__device__ __forceinline__ void fma2(u64& acc, u64 a, u64 b) {
    asm("fma.rn.f32x2 %0, %1, %2, %0;" : "+l"(acc) : "l"(a), "l"(b));
}
__device__ __forceinline__ void mul2(u64& a, u64 b) {
    asm("mul.rn.f32x2 %0, %0, %1;" : "+l"(a) : "l"(b));
}
__device__ __forceinline__ u64 pack2(float a) {
    u64 r;
    asm("mov.b64 %0, {%1, %1};" : "=l"(r) : "f"(a));
    return r;
}
__device__ __forceinline__ unsigned smem_u32(const void* p) {
    return (unsigned)__cvta_generic_to_shared(p);
}
__device__ __forceinline__ void cpa16(unsigned dst, const void* src) {
    asm volatile("cp.async.cg.shared.global [%0], [%1], 16;" :: "r"(dst), "l"(src));
}

// ---------------- scratch ----------------
__device__ float g_proj [N_ * NPROJ];
__device__ float g_qpt  [N_ * 144];
__device__ float g_kpt  [N_ * 144];
__device__ float g_vpt  [N_ * 288];
__device__ float g_qaug [N_ * H_ * 32];
__device__ float g_kaug [N_ * H_ * 32];
__device__ float g_L    [(long)N_ * H_ * 1024];
__device__ float g_feat [(long)N_ * NFEAT];

// ---------------- kernel A: fused projection GEMM ----------------
__global__ __launch_bounds__(256) void proj_gemm_kernel(
    const float* __restrict__ A,
    const float* __restrict__ wq,  const float* __restrict__ bq,
    const float* __restrict__ wkv, const float* __restrict__ bkv,
    const float* __restrict__ wqp, const float* __restrict__ bqp,
    const float* __restrict__ wkvp,const float* __restrict__ bkvp)
{
    __shared__ float As[16][64];
    __shared__ float Bs[16][68];
    int bm = blockIdx.x * 64, bn = blockIdx.y * 64;
    int tid = threadIdx.x;
    int tx = tid & 15, ty = tid >> 4;
    int lm = tid >> 2, lk4 = (tid & 3) * 4;
    int bk = tid >> 4, bn4 = (tid & 15) * 4;
    u64 acc01[4] = {0,0,0,0}, acc23[4] = {0,0,0,0};

    for (int k0 = 0; k0 < C1_; k0 += 16) {
        float4 av = *(const float4*)&A[(bm + lm) * C1_ + k0 + lk4];
        As[lk4+0][lm] = av.x; As[lk4+1][lm] = av.y;
        As[lk4+2][lm] = av.z; As[lk4+3][lm] = av.w;
        int kg = k0 + bk;
        #pragma unroll
        for (int jj = 0; jj < 4; jj++) {
            int j = bn + bn4 + jj;
            float v;
            if      (j < 192) v = wq  [kg * 192 + j];
            else if (j < 576) v = wkv [kg * 384 + (j - 192)];
            else if (j < 720) v = wqp [kg * 144 + (j - 576)];
            else              v = wkvp[kg * 432 + (j - 720)];
            Bs[bk][bn4 + jj] = v;
        }
        __syncthreads();
        #pragma unroll
        for (int kk = 0; kk < 16; kk++) {
            float4 a4 = *(const float4*)&As[kk][ty * 4];
            ulonglong2 b2 = *(const ulonglong2*)&Bs[kk][tx * 4];
            float a[4] = {a4.x, a4.y, a4.z, a4.w};
            #pragma unroll
            for (int i = 0; i < 4; i++) {
                u64 ai = pack2(a[i]);
                fma2(acc01[i], ai, b2.x);
                fma2(acc23[i], ai, b2.y);
            }
        }
        __syncthreads();
    }
    #pragma unroll
    for (int i = 0; i < 4; i++) {
        float2 lo = *(float2*)&acc01[i];
        float2 hi = *(float2*)&acc23[i];
        float accv[4] = {lo.x, lo.y, hi.x, hi.y};
        #pragma unroll
        for (int j = 0; j < 4; j++) {
            int jg = bn + tx * 4 + j;
            float bias;
            if      (jg < 192) bias = bq  [jg];
            else if (jg < 576) bias = bkv [jg - 192];
            else if (jg < 720) bias = bqp [jg - 576];
            else               bias = bkvp[jg - 720];
            g_proj[(bm + ty * 4 + i) * NPROJ + jg] = accv[j] + bias;
        }
    }
}

// ---------------- kernel B: transform + aug vectors ----------------
__global__ __launch_bounds__(192) void transform_kernel(
    const float* __restrict__ rot, const float* __restrict__ trans,
    const float* __restrict__ tpw)
{
    int n = blockIdx.x;
    int tid = threadIdx.x;
    __shared__ float sn2[192];

    const float* pr = g_proj + n * NPROJ;
    float r00 = rot[n*9+0], r01 = rot[n*9+1], r02 = rot[n*9+2];
    float r10 = rot[n*9+3], r11 = rot[n*9+4], r12 = rot[n*9+5];
    float r20 = rot[n*9+6], r21 = rot[n*9+7], r22 = rot[n*9+8];
    float t0 = trans[n*3+0], t1 = trans[n*3+1], t2 = trans[n*3+2];

    float nrm = 0.f;
    if (tid < 48) {
        int pp = tid;
        float px = pr[576 +       pp];
        float py = pr[576 +  48 + pp];
        float pz = pr[576 +  96 + pp];
        float gx = r00*px + r01*py + r02*pz + t0;
        float gy = r10*px + r11*py + r12*pz + t1;
        float gz = r20*px + r21*py + r22*pz + t2;
        int h = pp >> 2, p = pp & 3;
        float* o = g_qpt + n * 144 + h * 12 + p * 3;
        o[0] = gx; o[1] = gy; o[2] = gz;
        nrm = gx*gx + gy*gy + gz*gz;
    } else {
        int pp = tid - 48;
        float px = pr[720 +       pp];
        float py = pr[720 + 144 + pp];
        float pz = pr[720 + 288 + pp];
        float gx = r00*px + r01*py + r02*pz + t0;
        float gy = r10*px + r11*py + r12*pz + t1;
        float gz = r20*px + r21*py + r22*pz + t2;
        int h = pp / 12, r = pp % 12;
        if (r < 4) {
            float* o = g_kpt + n * 144 + h * 12 + r * 3;
            o[0] = gx; o[1] = gy; o[2] = gz;
            nrm = gx*gx + gy*gy + gz*gz;
        } else {
            float* o = g_vpt + n * 288 + h * 24 + (r - 4) * 3;
            o[0] = gx; o[1] = gy; o[2] = gz;
        }
    }
    sn2[tid] = nrm;
    __syncthreads();
    if (tid < H_) {
        int h = tid;
        float q2 = 0.f, k2 = 0.f;
        #pragma unroll
        for (int p = 0; p < 4; p++) q2 += sn2[h * 4 + p];
        #pragma unroll
        for (int r = 0; r < 4; r++) k2 += sn2[48 + h * 12 + r];

        float tp = tpw[h];
        float spv = tp > 20.f ? tp : log1pf(__expf(tp));
        float pw = PTW * spv;

        float* qa = g_qaug + (n * H_ + h) * 32;
        float* ka = g_kaug + (n * H_ + h) * 32;
        #pragma unroll
        for (int c = 0; c < 16; c++) {
            qa[c] = SCW * pr[h * 16 + c];
            ka[c] = pr[192 + h * 32 + c];
        }
        #pragma unroll
        for (int c = 0; c < 12; c++) {
            qa[16 + c] = pw * g_qpt[n * 144 + h * 12 + c];
            ka[16 + c] = g_kpt[n * 144 + h * 12 + c];
        }
        qa[28] = -0.5f * pw * q2; qa[29] = 1.f; qa[30] = 0.f; qa[31] = 0.f;
        ka[28] = 1.f; ka[29] = -0.5f * pw * k2; ka[30] = 0.f; ka[31] = 0.f;
    }
}

// ---------------- kernel C: a2d streaming ----------------
__global__ __launch_bounds__(128) void a2d_kernel(
    const float* __restrict__ in2d, const float* __restrict__ w2d,
    const float* __restrict__ b2d)
{
    extern __shared__ float smC[];
    float* sd = smC;
    float* sw = smC + 128 * PITCH;

    int tid = threadIdx.x;
    int n = blockIdx.y;
    int m0 = blockIdx.x * 128;

    for (int i = tid; i < H_ * C2_; i += 128)
        sw[i] = w2d[(i & 127) * H_ + (i >> 7)] * W2DS;

    const float4* g = (const float4*)(in2d + ((long)n * N_ + m0) * C2_);
    for (int i = tid; i < 128 * 32; i += 128) {
        int row = i >> 5, c4 = i & 31;
        float4 v = g[i];
        *(float4*)&sd[row * PITCH + c4 * 4] = v;
    }
    __syncthreads();

    u64 acc[12];
    #pragma unroll
    for (int h = 0; h < 12; h++) acc[h] = 0ULL;

    const ulonglong2* drow = (const ulonglong2*)(sd + tid * PITCH);
    const ulonglong2* swp  = (const ulonglong2*)sw;

    #pragma unroll 4
    for (int c4 = 0; c4 < 32; c4++) {
        ulonglong2 d = drow[c4];
        #pragma unroll
        for (int h = 0; h < 12; h++) {
            ulonglong2 w = swp[h * 32 + c4];
            fma2(acc[h], d.x, w.x);
            fma2(acc[h], d.y, w.y);
        }
    }
    #pragma unroll
    for (int h = 0; h < 12; h++) {
        float2 a = *(float2*)&acc[h];
        g_L[((long)n * H_ + h) * N_ + m0 + tid] = a.x + a.y + b2d[h] * W2DS;
    }
}

// ---------------- kernel D: qk logits GEMM + mask, RMW into L ----------------
__global__ __launch_bounds__(256) void qk_kernel(const float* __restrict__ mask)
{
    __shared__ float Aq[32][68];
    __shared__ float Bk[32][68];
    int h  = blockIdx.z;
    int nb = blockIdx.y * 64, mb = blockIdx.x * 64;
    int tid = threadIdx.x;

    for (int i = tid; i < 64 * 8; i += 256) {
        int row = i >> 3, k4 = (i & 7) * 4;
        float4 q = *(const float4*)&g_qaug[((nb + row) * H_ + h) * 32 + k4];
        Aq[k4+0][row] = q.x; Aq[k4+1][row] = q.y; Aq[k4+2][row] = q.z; Aq[k4+3][row] = q.w;
        float4 k = *(const float4*)&g_kaug[((mb + row) * H_ + h) * 32 + k4];
        Bk[k4+0][row] = k.x; Bk[k4+1][row] = k.y; Bk[k4+2][row] = k.z; Bk[k4+3][row] = k.w;
    }
    __syncthreads();

    int tx = tid & 15, ty = tid >> 4;
    float acc[4][4] = {};
    #pragma unroll
    for (int k = 0; k < 32; k++) {
        float4 a4 = *(const float4*)&Aq[k][ty * 4];
        float4 b4 = *(const float4*)&Bk[k][tx * 4];
        float a[4] = {a4.x, a4.y, a4.z, a4.w};
        float b[4] = {b4.x, b4.y, b4.z, b4.w};
        #pragma unroll
        for (int i = 0; i < 4; i++)
            #pragma unroll
            for (int j = 0; j < 4; j++)
                acc[i][j] += a[i] * b[j];
    }
    float mm[4], mn[4];
    #pragma unroll
    for (int j = 0; j < 4; j++) mm[j] = mask[mb + tx * 4 + j];
    #pragma unroll
    for (int i = 0; i < 4; i++) mn[i] = mask[nb + ty * 4 + i];

    #pragma unroll
    for (int i = 0; i < 4; i++) {
        float* p = &g_L[((long)(nb + ty * 4 + i) * H_ + h) * N_ + mb + tx * 4];
        float4 L4 = *(float4*)p;
        L4.x += acc[i][0] - 100000.f * (1.f - mn[i] * mm[0]);
        L4.y += acc[i][1] - 100000.f * (1.f - mn[i] * mm[1]);
        L4.z += acc[i][2] - 100000.f * (1.f - mn[i] * mm[2]);
        L4.w += acc[i][3] - 100000.f * (1.f - mn[i] * mm[3]);
        *(float4*)p = L4;
    }
}

// ---------------- kernel E: attention (cp.async double-buffered, QB=2) ----------------
__global__ void __launch_bounds__(384, 2) attn_kernel(
    const float* __restrict__ in2d,
    const float* __restrict__ rot, const float* __restrict__ trans)
{
    extern __shared__ float sm[];
    float* s2d  = sm;                        // 2 * 8448
    float* sp   = sm + 2 * BUFF;             // 12*32*2 [h][mi][q]
    float* sinv = sp + H_ * TM * QB;         // 24

    int tid  = threadIdx.x;
    int h    = tid >> 5;
    int lane = tid & 31;
    int n0   = blockIdx.x * QB;

    int c4 = tid & 31;
    int hp = (tid >> 5) % 6;
    int mq = tid / 192;
    int h0 = hp * 2;

    unsigned s2d_sm = smem_u32(s2d);
    const float4* g2d = (const float4*)in2d;

    ulonglong2 a2[2][QB];
    #pragma unroll
    for (int hh = 0; hh < 2; hh++)
        #pragma unroll
        for (int q = 0; q < QB; q++) a2[hh][q] = make_ulonglong2(0ULL, 0ULL);
    float accs[QB] = {}, accp[QB] = {};
    float srun[QB] = {};

    // prefetch tile 0 into buffer 0
    for (int i = tid; i < QB * TM * 32; i += 384) {
        int q = i >> 10, r = i & 1023;
        int mi = r >> 5, cc = r & 31;
        cpa16(s2d_sm + ((q * TM + mi) * PITCH + cc * 4) * 4,
              &g2d[((long)(n0 + q) * N_ + mi) * 32 + cc]);
    }
    asm volatile("cp.async.commit_group;");

    for (int t = 0; t < N_ / TM; t++) {
        int m0 = t * TM;
        int cur = t & 1;
        int m = m0 + lane;

        // prefetch logits for this tile (regs)
        float lg[QB];
        #pragma unroll
        for (int q = 0; q < QB; q++)
            lg[q] = g_L[((long)(n0 + q) * H_ + h) * N_ + m];

        // stage next tile into alternate buffer
        if (t + 1 < N_ / TM) {
            unsigned dstb = s2d_sm + (1 - cur) * BUFF * 4;
            for (int i = tid; i < QB * TM * 32; i += 384) {
                int q = i >> 10, r = i & 1023;
                int mi = r >> 5, cc = r & 31;
                cpa16(dstb + ((q * TM + mi) * PITCH + cc * 4) * 4,
                      &g2d[((long)(n0 + q) * N_ + m0 + TM + mi) * 32 + cc]);
            }
        }
        asm volatile("cp.async.commit_group;");

        // phase 2: p = exp(L)
        float pv[QB];
        #pragma unroll
        for (int q = 0; q < QB; q++) {
            pv[q] = __expf(lg[q]);
            srun[q] += pv[q];
        }
        asm volatile("cp.async.wait_group 1;");
        *(float2*)&sp[((h << 5) + lane) << 1] = make_float2(pv[0], pv[1]);
        __syncthreads();

        const float* buf = s2d + cur * BUFF;
        const ulonglong2* s2d8 = (const ulonglong2*)buf;

        // phase 3: attn_2d (2 heads/thread, m-split)
        {
            int mbeg = mq * 16;
            #pragma unroll 4
            for (int mi = mbeg; mi < mbeg + 16; mi++) {
                float2 pa = *(const float2*)&sp[((h0 << 5) + mi) << 1];
                float2 pb = *(const float2*)&sp[(((h0 + 1) << 5) + mi) << 1];
                const float* paf = (const float*)&pa;
                const float* pbf = (const float*)&pb;
                #pragma unroll
                for (int q = 0; q < QB; q++) {
                    u64 p0 = pack2(paf[q]);
                    u64 p1 = pack2(pbf[q]);
                    ulonglong2 d = s2d8[(q * TM + mi) * 33 + c4];
                    fma2(a2[0][q].x, p0, d.x);
                    fma2(a2[0][q].y, p0, d.y);
                    fma2(a2[1][q].x, p1, d.x);
                    fma2(a2[1][q].y, p1, d.y);
                }
            }
        }

        // phase 2b: res_scalar / res_point
        {
            float vsc = 0.f, vpc = 0.f;
            #pragma unroll 8
            for (int mi = 0; mi < TM; mi++) {
                int mm = m0 + mi;
                if (lane < 16) vsc = g_proj[mm * NPROJ + 192 + h * 32 + 16 + lane];
                if (lane < 24) vpc = g_vpt[mm * 288 + h * 24 + lane];
                float2 p2 = *(const float2*)&sp[((h << 5) + mi) << 1];
                accs[0] += p2.x * vsc; accp[0] += p2.x * vpc;
                accs[1] += p2.y * vsc; accp[1] += p2.y * vpc;
            }
        }
        __syncthreads();
    }

    // ---- epilogue ----
    float inv[QB];
    #pragma unroll
    for (int q = 0; q < QB; q++) {
        float s = srun[q];
        #pragma unroll
        for (int o = 16; o > 0; o >>= 1)
            s += __shfl_xor_sync(0xffffffffu, s, o);
        inv[q] = 1.f / s;
        if (lane == 0) sinv[q * H_ + h] = inv[q];
        if (lane < 16) g_feat[(long)(n0 + q) * NFEAT + h * 16 + lane] = accs[q] * inv[q];
    }
    #pragma unroll
    for (int q = 0; q < QB; q++) {
        int n = n0 + q;
        float* f = g_feat + (long)n * NFEAT;
        __syncwarp();
        if (lane < 24) sp[h * 64 + lane] = accp[q] * inv[q];
        __syncwarp();
        if (lane < 8) {
            int p = lane;
            float gx = sp[h * 64 + p * 3 + 0] - trans[n * 3 + 0];
            float gy = sp[h * 64 + p * 3 + 1] - trans[n * 3 + 1];
            float gz = sp[h * 64 + p * 3 + 2] - trans[n * 3 + 2];
            float lx = rot[n*9+0]*gx + rot[n*9+3]*gy + rot[n*9+6]*gz;
            float ly = rot[n*9+1]*gx + rot[n*9+4]*gy + rot[n*9+7]*gz;
            float lz = rot[n*9+2]*gx + rot[n*9+5]*gy + rot[n*9+8]*gz;
            float d  = sqrtf(1e-8f + lx*lx + ly*ly + lz*lz);
            f[192 + h * 8 + p] = lx;
            f[288 + h * 8 + p] = ly;
            f[384 + h * 8 + p] = lz;
            f[480 + h * 8 + p] = d;
        }
        __syncwarp();
    }
    __syncthreads();

    float4* red = (float4*)s2d;
    #pragma unroll
    for (int hh = 0; hh < 2; hh++) {
        __syncthreads();
        #pragma unroll
        for (int q = 0; q < QB; q++) {
            u64 iv2 = pack2(sinv[q * H_ + h0 + hh]);
            u64 vx = a2[hh][q].x, vy = a2[hh][q].y;
            mul2(vx, iv2); mul2(vy, iv2);
            float2 lo = *(float2*)&vx;
            float2 hi = *(float2*)&vy;
            red[(q * 2 + mq) * 192 + hp * 32 + c4] = make_float4(lo.x, lo.y, hi.x, hi.y);
        }
        __syncthreads();
        if (mq == 0) {
            #pragma unroll
            for (int q = 0; q < QB; q++) {
                float4 a = red[(q * 2    ) * 192 + hp * 32 + c4];
                float4 b = red[(q * 2 + 1) * 192 + hp * 32 + c4];
                a.x += b.x; a.y += b.y; a.z += b.z; a.w += b.w;
                *(float4*)&g_feat[(long)(n0 + q) * NFEAT + 576 + (h0 + hh) * 128 + c4 * 4] = a;
            }
        }
    }
}

// ---------------- kernel F: output GEMM ----------------
__global__ __launch_bounds__(1024) void out_gemm_kernel(
    const float* __restrict__ B, const float* __restrict__ bias,
    float* __restrict__ C)
{
    __shared__ float As[4][16][64];
    __shared__ float Bs[4][16][36];
    int tid = threadIdx.x;
    int g = tid >> 8;
    int t = tid & 255;
    int bm = blockIdx.x * 64, bn = blockIdx.y * 32;
    int tx = t & 15, ty = t >> 4;
    int lm = t >> 2, lk4 = (t & 3) * 4;
    u64 acc[4] = {0,0,0,0};

    int kbase = g * 528;
    for (int kk0 = 0; kk0 < 528; kk0 += 16) {
        int k0 = kbase + kk0;
        float4 av = *(const float4*)&g_feat[(long)(bm + lm) * NFEAT + k0 + lk4];
        As[g][lk4+0][lm] = av.x; As[g][lk4+1][lm] = av.y;
        As[g][lk4+2][lm] = av.z; As[g][lk4+3][lm] = av.w;
        if (t < 128) {
            int bk = t >> 3, bn4 = (t & 7) * 4;
            float4 bv = *(const float4*)&B[(long)(k0 + bk) * COUT_ + bn + bn4];
            *(float4*)&Bs[g][bk][bn4] = bv;
        }
        __syncthreads();
        #pragma unroll
        for (int kk = 0; kk < 16; kk++) {
            float4 a4 = *(const float4*)&As[g][kk][ty * 4];
            u64 b = *(const u64*)&Bs[g][kk][tx * 2];
            fma2(acc[0], pack2(a4.x), b);
            fma2(acc[1], pack2(a4.y), b);
            fma2(acc[2], pack2(a4.z), b);
            fma2(acc[3], pack2(a4.w), b);
        }
        __syncthreads();
    }

    float* red = &As[0][0][0];
    #pragma unroll
    for (int r = 0; r < 2; r++) {
        __syncthreads();
        if (g > 0) {
            float2 p0 = *(float2*)&acc[r * 2];
            float2 p1 = *(float2*)&acc[r * 2 + 1];
            *(float4*)&red[((g - 1) * 256 + t) * 4] = make_float4(p0.x, p0.y, p1.x, p1.y);
        }
        __syncthreads();
        if (g == 0) {
            #pragma unroll
            for (int gg = 0; gg < 3; gg++) {
                float4 v = *(float4*)&red[(gg * 256 + t) * 4];
                float2 p0 = *(float2*)&acc[r * 2];
                float2 p1 = *(float2*)&acc[r * 2 + 1];
                p0.x += v.x; p0.y += v.y; p1.x += v.z; p1.y += v.w;
                *(float2*)&acc[r * 2]     = p0;
                *(float2*)&acc[r * 2 + 1] = p1;
            }
        }
    }
    if (g == 0) {
        float b0 = bias[bn + tx * 2], b1 = bias[bn + tx * 2 + 1];
        #pragma unroll
        for (int i = 0; i < 4; i++) {
            float2 v = *(float2*)&acc[i];
            v.x += b0; v.y += b1;
            *(float2*)&C[(long)(bm + ty * 4 + i) * COUT_ + bn + tx * 2] = v;
        }
    }
}

// ---------------- launch ----------------
extern "C" void kernel_launch(void* const* d_in, const int* in_sizes, int n_in,
                              void* d_out, int out_size)
{
    const float* inputs_1d = (const float*)d_in[0];
    const float* inputs_2d = (const float*)d_in[1];
    const float* mask      = (const float*)d_in[2];
    const float* rot       = (const float*)d_in[3];
    const float* trans     = (const float*)d_in[4];
    const float* wq        = (const float*)d_in[5];
    const float* bq        = (const float*)d_in[6];
    const float* wkv       = (const float*)d_in[7];
    const float* bkv       = (const float*)d_in[8];
    const float* wqp       = (const float*)d_in[9];
    const float* bqp       = (const float*)d_in[10];
    const float* wkvp      = (const float*)d_in[11];
    const float* bkvp      = (const float*)d_in[12];
    const float* w2d       = (const float*)d_in[13];
    const float* b2d       = (const float*)d_in[14];
    const float* tpw       = (const float*)d_in[15];
    const float* wout      = (const float*)d_in[16];
    const float* bout      = (const float*)d_in[17];
    float* out = (float*)d_out;

    proj_gemm_kernel<<<dim3(16, 18), 256>>>(inputs_1d, wq, bq, wkv, bkv,
                                            wqp, bqp, wkvp, bkvp);
    transform_kernel<<<N_, 192>>>(rot, trans, tpw);

    int smemC = (128 * PITCH + H_ * C2_) * (int)sizeof(float);
    cudaFuncSetAttribute(a2d_kernel, cudaFuncAttributeMaxDynamicSharedMemorySize, smemC);
    a2d_kernel<<<dim3(8, N_), 128, smemC>>>(inputs_2d, w2d, b2d);

    qk_kernel<<<dim3(16, 16, 12), 256>>>(mask);

    int smemE = (2 * BUFF + H_ * TM * QB + QB * H_) * (int)sizeof(float);
    cudaFuncSetAttribute(attn_kernel, cudaFuncAttributeMaxDynamicSharedMemorySize, smemE);
    attn_kernel<<<N_ / QB, 384, smemE>>>(inputs_2d, rot, trans);

    out_gemm_kernel<<<dim3(16, 12), 1024>>>(wout, bout, out);
}

// round 8
// speedup vs baseline: 2.0562x; 2.0562x over previous
#include <cuda_runtime.h>
#include <math.h>

#define N_    1024
#define H_    12
#define C1_   384
#define C2_   128
#define COUT_ 384
#define NPROJ 1152
#define NFEAT 2112
#define QB    4
#define TM    32
#define PITCH 132

#define W2DS 0.5773502691896258f
#define SCW  0.14433756729740643f
#define PTW  0.1360827634879543f

typedef unsigned long long u64;

__device__ __forceinline__ void fma2(u64& acc, u64 a, u64 b) {
    asm("fma.rn.f32x2 %0, %1, %2, %0;" : "+l"(acc) : "l"(a), "l"(b));
}
__device__ __forceinline__ void mul2(u64& a, u64 b) {
    asm("mul.rn.f32x2 %0, %0, %1;" : "+l"(a) : "l"(b));
}
__device__ __forceinline__ u64 pack2(float a) {
    u64 r;
    asm("mov.b64 %0, {%1, %1};" : "=l"(r) : "f"(a));
    return r;
}
__device__ __forceinline__ unsigned smem_u32(const void* p) {
    return (unsigned)__cvta_generic_to_shared(p);
}
__device__ __forceinline__ void cpa16(unsigned dst, const void* src) {
    asm volatile("cp.async.cg.shared.global [%0], [%1], 16;" :: "r"(dst), "l"(src));
}

// ---------------- scratch ----------------
__device__ float g_proj [N_ * NPROJ];
__device__ float g_qpt  [N_ * 144];
__device__ float g_kpt  [N_ * 144];
__device__ float g_vpt  [N_ * 288];
__device__ float g_qaug [N_ * H_ * 32];
__device__ float g_kaug [N_ * H_ * 32];
__device__ float g_P    [(long)N_ * H_ * 1024];   // logits -> unnormalized probs
__device__ float g_iv   [N_ * H_];
__device__ float g_vm   [(long)N_ * H_ * 64];     // merged v (32 u64/row, padded)
__device__ float g_feat [(long)N_ * NFEAT];

// ---------------- kernel A: fused projection GEMM ----------------
__global__ __launch_bounds__(256) void proj_gemm_kernel(
    const float* __restrict__ A,
    const float* __restrict__ wq,  const float* __restrict__ bq,
    const float* __restrict__ wkv, const float* __restrict__ bkv,
    const float* __restrict__ wqp, const float* __restrict__ bqp,
    const float* __restrict__ wkvp,const float* __restrict__ bkvp)
{
    __shared__ float As[16][64];
    __shared__ float Bs[16][68];
    int bm = blockIdx.x * 64, bn = blockIdx.y * 64;
    int tid = threadIdx.x;
    int tx = tid & 15, ty = tid >> 4;
    int lm = tid >> 2, lk4 = (tid & 3) * 4;
    int bk = tid >> 4, bn4 = (tid & 15) * 4;
    u64 acc01[4] = {0,0,0,0}, acc23[4] = {0,0,0,0};

    for (int k0 = 0; k0 < C1_; k0 += 16) {
        float4 av = *(const float4*)&A[(bm + lm) * C1_ + k0 + lk4];
        As[lk4+0][lm] = av.x; As[lk4+1][lm] = av.y;
        As[lk4+2][lm] = av.z; As[lk4+3][lm] = av.w;
        int kg = k0 + bk;
        #pragma unroll
        for (int jj = 0; jj < 4; jj++) {
            int j = bn + bn4 + jj;
            float v;
            if      (j < 192) v = wq  [kg * 192 + j];
            else if (j < 576) v = wkv [kg * 384 + (j - 192)];
            else if (j < 720) v = wqp [kg * 144 + (j - 576)];
            else              v = wkvp[kg * 432 + (j - 720)];
            Bs[bk][bn4 + jj] = v;
        }
        __syncthreads();
        #pragma unroll
        for (int kk = 0; kk < 16; kk++) {
            float4 a4 = *(const float4*)&As[kk][ty * 4];
            ulonglong2 b2 = *(const ulonglong2*)&Bs[kk][tx * 4];
            float a[4] = {a4.x, a4.y, a4.z, a4.w};
            #pragma unroll
            for (int i = 0; i < 4; i++) {
                u64 ai = pack2(a[i]);
                fma2(acc01[i], ai, b2.x);
                fma2(acc23[i], ai, b2.y);
            }
        }
        __syncthreads();
    }
    #pragma unroll
    for (int i = 0; i < 4; i++) {
        float2 lo = *(float2*)&acc01[i];
        float2 hi = *(float2*)&acc23[i];
        float accv[4] = {lo.x, lo.y, hi.x, hi.y};
        #pragma unroll
        for (int j = 0; j < 4; j++) {
            int jg = bn + tx * 4 + j;
            float bias;
            if      (jg < 192) bias = bq  [jg];
            else if (jg < 576) bias = bkv [jg - 192];
            else if (jg < 720) bias = bqp [jg - 576];
            else               bias = bkvp[jg - 720];
            g_proj[(bm + ty * 4 + i) * NPROJ + jg] = accv[j] + bias;
        }
    }
}

// ---------------- kernel B: transform + aug vectors + merged v ----------------
__global__ __launch_bounds__(192) void transform_kernel(
    const float* __restrict__ rot, const float* __restrict__ trans,
    const float* __restrict__ tpw)
{
    int n = blockIdx.x;
    int tid = threadIdx.x;
    __shared__ float sn2[192];

    const float* pr = g_proj + n * NPROJ;
    float r00 = rot[n*9+0], r01 = rot[n*9+1], r02 = rot[n*9+2];
    float r10 = rot[n*9+3], r11 = rot[n*9+4], r12 = rot[n*9+5];
    float r20 = rot[n*9+6], r21 = rot[n*9+7], r22 = rot[n*9+8];
    float t0 = trans[n*3+0], t1 = trans[n*3+1], t2 = trans[n*3+2];

    float nrm = 0.f;
    if (tid < 48) {
        int pp = tid;
        float px = pr[576 +       pp];
        float py = pr[576 +  48 + pp];
        float pz = pr[576 +  96 + pp];
        float gx = r00*px + r01*py + r02*pz + t0;
        float gy = r10*px + r11*py + r12*pz + t1;
        float gz = r20*px + r21*py + r22*pz + t2;
        int h = pp >> 2, p = pp & 3;
        float* o = g_qpt + n * 144 + h * 12 + p * 3;
        o[0] = gx; o[1] = gy; o[2] = gz;
        nrm = gx*gx + gy*gy + gz*gz;
    } else {
        int pp = tid - 48;
        float px = pr[720 +       pp];
        float py = pr[720 + 144 + pp];
        float pz = pr[720 + 288 + pp];
        float gx = r00*px + r01*py + r02*pz + t0;
        float gy = r10*px + r11*py + r12*pz + t1;
        float gz = r20*px + r21*py + r22*pz + t2;
        int h = pp / 12, r = pp % 12;
        if (r < 4) {
            float* o = g_kpt + n * 144 + h * 12 + r * 3;
            o[0] = gx; o[1] = gy; o[2] = gz;
            nrm = gx*gx + gy*gy + gz*gz;
        } else {
            float* o = g_vpt + n * 288 + h * 24 + (r - 4) * 3;
            o[0] = gx; o[1] = gy; o[2] = gz;
        }
    }
    sn2[tid] = nrm;
    __syncthreads();
    if (tid < H_) {
        int h = tid;
        float q2 = 0.f, k2 = 0.f;
        #pragma unroll
        for (int p = 0; p < 4; p++) q2 += sn2[h * 4 + p];
        #pragma unroll
        for (int r = 0; r < 4; r++) k2 += sn2[48 + h * 12 + r];

        float tp = tpw[h];
        float spv = tp > 20.f ? tp : log1pf(__expf(tp));
        float pw = PTW * spv;

        float* qa = g_qaug + (n * H_ + h) * 32;
        float* ka = g_kaug + (n * H_ + h) * 32;
        #pragma unroll
        for (int c = 0; c < 16; c++) {
            qa[c] = SCW * pr[h * 16 + c];
            ka[c] = pr[192 + h * 32 + c];
        }
        #pragma unroll
        for (int c = 0; c < 12; c++) {
            qa[16 + c] = pw * g_qpt[n * 144 + h * 12 + c];
            ka[16 + c] = g_kpt[n * 144 + h * 12 + c];
        }
        qa[28] = -0.5f * pw * q2; qa[29] = 1.f; qa[30] = 0.f; qa[31] = 0.f;
        ka[28] = 1.f; ka[29] = -0.5f * pw * k2; ka[30] = 0.f; ka[31] = 0.f;

        // merged v: [m][h][32 u64]: j<8 -> vs pairs, 8<=j<20 -> vp pairs, rest 0
        float2* vm = (float2*)&g_vm[((long)n * H_ + h) * 64];
        #pragma unroll
        for (int j = 0; j < 8; j++)
            vm[j] = make_float2(pr[192 + h * 32 + 16 + 2*j],
                                pr[192 + h * 32 + 16 + 2*j + 1]);
        #pragma unroll
        for (int j = 8; j < 20; j++)
            vm[j] = make_float2(g_vpt[n * 288 + h * 24 + 2*(j-8)],
                                g_vpt[n * 288 + h * 24 + 2*(j-8) + 1]);
        #pragma unroll
        for (int j = 20; j < 32; j++)
            vm[j] = make_float2(0.f, 0.f);
    }
}

// ---------------- kernel C: a2d streaming (writes logits base into g_P) ----------------
__global__ __launch_bounds__(128) void a2d_kernel(
    const float* __restrict__ in2d, const float* __restrict__ w2d,
    const float* __restrict__ b2d)
{
    extern __shared__ float smC[];
    float* sd = smC;
    float* sw = smC + 128 * PITCH;

    int tid = threadIdx.x;
    int n = blockIdx.y;
    int m0 = blockIdx.x * 128;

    for (int i = tid; i < H_ * C2_; i += 128)
        sw[i] = w2d[(i & 127) * H_ + (i >> 7)] * W2DS;

    const float4* g = (const float4*)(in2d + ((long)n * N_ + m0) * C2_);
    for (int i = tid; i < 128 * 32; i += 128) {
        int row = i >> 5, c4 = i & 31;
        float4 v = g[i];
        *(float4*)&sd[row * PITCH + c4 * 4] = v;
    }
    __syncthreads();

    u64 acc[12];
    #pragma unroll
    for (int h = 0; h < 12; h++) acc[h] = 0ULL;

    const ulonglong2* drow = (const ulonglong2*)(sd + tid * PITCH);
    const ulonglong2* swp  = (const ulonglong2*)sw;

    #pragma unroll 4
    for (int c4 = 0; c4 < 32; c4++) {
        ulonglong2 d = drow[c4];
        #pragma unroll
        for (int h = 0; h < 12; h++) {
            ulonglong2 w = swp[h * 32 + c4];
            fma2(acc[h], d.x, w.x);
            fma2(acc[h], d.y, w.y);
        }
    }
    #pragma unroll
    for (int h = 0; h < 12; h++) {
        float2 a = *(float2*)&acc[h];
        g_P[((long)n * H_ + h) * N_ + m0 + tid] = a.x + a.y + b2d[h] * W2DS;
    }
}

// ---------------- kernel D: qk GEMM + mask + EXP (in place into g_P) ----------------
__global__ __launch_bounds__(256) void qk_kernel(const float* __restrict__ mask)
{
    __shared__ float Aq[32][68];
    __shared__ float Bk[32][68];
    int h  = blockIdx.z;
    int nb = blockIdx.y * 64, mb = blockIdx.x * 64;
    int tid = threadIdx.x;

    for (int i = tid; i < 64 * 8; i += 256) {
        int row = i >> 3, k4 = (i & 7) * 4;
        float4 q = *(const float4*)&g_qaug[((nb + row) * H_ + h) * 32 + k4];
        Aq[k4+0][row] = q.x; Aq[k4+1][row] = q.y; Aq[k4+2][row] = q.z; Aq[k4+3][row] = q.w;
        float4 k = *(const float4*)&g_kaug[((mb + row) * H_ + h) * 32 + k4];
        Bk[k4+0][row] = k.x; Bk[k4+1][row] = k.y; Bk[k4+2][row] = k.z; Bk[k4+3][row] = k.w;
    }
    __syncthreads();

    int tx = tid & 15, ty = tid >> 4;
    float acc[4][4] = {};
    #pragma unroll
    for (int k = 0; k < 32; k++) {
        float4 a4 = *(const float4*)&Aq[k][ty * 4];
        float4 b4 = *(const float4*)&Bk[k][tx * 4];
        float a[4] = {a4.x, a4.y, a4.z, a4.w};
        float b[4] = {b4.x, b4.y, b4.z, b4.w};
        #pragma unroll
        for (int i = 0; i < 4; i++)
            #pragma unroll
            for (int j = 0; j < 4; j++)
                acc[i][j] += a[i] * b[j];
    }
    float mm[4], mn[4];
    #pragma unroll
    for (int j = 0; j < 4; j++) mm[j] = mask[mb + tx * 4 + j];
    #pragma unroll
    for (int i = 0; i < 4; i++) mn[i] = mask[nb + ty * 4 + i];

    #pragma unroll
    for (int i = 0; i < 4; i++) {
        float* p = &g_P[((long)(nb + ty * 4 + i) * H_ + h) * N_ + mb + tx * 4];
        float4 L4 = *(float4*)p;
        L4.x = __expf(L4.x + acc[i][0] - 100000.f * (1.f - mn[i] * mm[0]));
        L4.y = __expf(L4.y + acc[i][1] - 100000.f * (1.f - mn[i] * mm[1]));
        L4.z = __expf(L4.z + acc[i][2] - 100000.f * (1.f - mn[i] * mm[2]));
        L4.w = __expf(L4.w + acc[i][3] - 100000.f * (1.f - mn[i] * mm[3]));
        *(float4*)p = L4;
    }
}

// ---------------- kernel D2: 1/rowsum ----------------
__global__ __launch_bounds__(256) void stats_kernel()
{
    int row  = blockIdx.x * 8 + (threadIdx.x >> 5);
    int lane = threadIdx.x & 31;
    const float4* Pr = (const float4*)(g_P + (long)row * N_);
    float s = 0.f;
    #pragma unroll
    for (int j = 0; j < 8; j++) {
        float4 v = Pr[j * 32 + lane];
        s += v.x + v.y + v.z + v.w;
    }
    #pragma unroll
    for (int o = 16; o > 0; o >>= 1)
        s += __shfl_xor_sync(0xffffffffu, s, o);
    if (lane == 0) g_iv[row] = 1.f / s;
}

// ---------------- kernel E: attention accumulation (instruction diet) ----------------
__global__ void __launch_bounds__(384, 2) attn_kernel(
    const float* __restrict__ in2d,
    const float* __restrict__ rot, const float* __restrict__ trans)
{
    extern __shared__ float sm[];
    float* s2d  = sm;                       // 16896
    float* sp2  = sm + QB * TM * PITCH;     // 4*12*32*2 = 3072
    float* sinv = sp2 + QB * H_ * 64;       // 48

    int tid  = threadIdx.x;
    int h    = tid >> 5;
    int lane = tid & 31;
    int n0   = blockIdx.x * QB;

    int c4 = tid & 31;
    int hp = (tid >> 5) % 6;
    int mq = tid / 192;
    int h0 = hp * 2;

    unsigned s2d_sm = smem_u32(s2d);
    const float4* g2d = (const float4*)in2d;
    const u64* vm64 = (const u64*)g_vm;

    ulonglong2 a2[2][QB];
    #pragma unroll
    for (int hh = 0; hh < 2; hh++)
        #pragma unroll
        for (int q = 0; q < QB; q++) a2[hh][q] = make_ulonglong2(0ULL, 0ULL);
    u64 acc2b[QB] = {0,0,0,0};

    for (int t = 0; t < N_ / TM; t++) {
        int m0 = t * TM;
        int m = m0 + lane;

        // stage tile (cp.async, single buffer)
        for (int i = tid; i < QB * TM * 32; i += 384) {
            int q = i >> 10, r = i & 1023;
            int mi = r >> 5, cc = r & 31;
            cpa16(s2d_sm + ((q * TM + mi) * PITCH + cc * 4) * 4,
                  &g2d[((long)(n0 + q) * N_ + m0 + mi) * 32 + cc]);
        }
        asm volatile("cp.async.commit_group;");

        // load unnormalized probs (overlap with staging)
        float pv[QB];
        #pragma unroll
        for (int q = 0; q < QB; q++)
            pv[q] = g_P[((long)(n0 + q) * H_ + h) * N_ + m];

        asm volatile("cp.async.wait_group 0;");
        #pragma unroll
        for (int q = 0; q < QB; q++)
            *(float2*)&sp2[((q * H_ + h) * 32 + lane) * 2] = make_float2(pv[q], pv[q]);
        __syncthreads();

        // phase 3: attn_2d (2 heads/thread, m-split, u64 p loads)
        {
            const ulonglong2* s2d8 = (const ulonglong2*)s2d;
            int mbeg = mq * 16;
            #pragma unroll 4
            for (int mi = mbeg; mi < mbeg + 16; mi++) {
                #pragma unroll
                for (int q = 0; q < QB; q++) {
                    u64 p0 = *(const u64*)&sp2[((q * H_ + h0    ) * 32 + mi) * 2];
                    u64 p1 = *(const u64*)&sp2[((q * H_ + h0 + 1) * 32 + mi) * 2];
                    ulonglong2 d = s2d8[(q * TM + mi) * 33 + c4];
                    fma2(a2[0][q].x, p0, d.x);
                    fma2(a2[0][q].y, p0, d.y);
                    fma2(a2[1][q].x, p1, d.x);
                    fma2(a2[1][q].y, p1, d.y);
                }
            }
        }

        // phase 2b: merged-v accumulation (lane = u64 channel pair)
        {
            const u64* vrow = vm64 + ((long)m0 * H_ + h) * 32 + lane;
            #pragma unroll 8
            for (int mi = 0; mi < TM; mi++) {
                u64 v = vrow[(long)mi * H_ * 32];
                #pragma unroll
                for (int q = 0; q < QB; q++) {
                    u64 p = *(const u64*)&sp2[((q * H_ + h) * 32 + mi) * 2];
                    fma2(acc2b[q], p, v);
                }
            }
        }
        __syncthreads();
    }

    // ---- epilogue ----
    float inv[QB];
    #pragma unroll
    for (int q = 0; q < QB; q++) {
        inv[q] = g_iv[(n0 + q) * H_ + h];
        if (lane == 0) sinv[q * H_ + h] = inv[q];
    }
    #pragma unroll
    for (int q = 0; q < QB; q++) {
        int n = n0 + q;
        float* f = g_feat + (long)n * NFEAT;
        float2 ac = *(float2*)&acc2b[q];
        ac.x *= inv[q]; ac.y *= inv[q];
        if (lane < 8) {               // res_scalar ch 2l, 2l+1
            f[h * 16 + 2 * lane]     = ac.x;
            f[h * 16 + 2 * lane + 1] = ac.y;
        }
        __syncwarp();
        if (lane >= 8 && lane < 20) { // res_point ch 2(l-8), +1 -> smem
            sp2[h * 64 + 2 * (lane - 8)]     = ac.x;
            sp2[h * 64 + 2 * (lane - 8) + 1] = ac.y;
        }
        __syncwarp();
        if (lane < 8) {
            int p = lane;
            float gx = sp2[h * 64 + p * 3 + 0] - trans[n * 3 + 0];
            float gy = sp2[h * 64 + p * 3 + 1] - trans[n * 3 + 1];
            float gz = sp2[h * 64 + p * 3 + 2] - trans[n * 3 + 2];
            float lx = rot[n*9+0]*gx + rot[n*9+3]*gy + rot[n*9+6]*gz;
            float ly = rot[n*9+1]*gx + rot[n*9+4]*gy + rot[n*9+7]*gz;
            float lz = rot[n*9+2]*gx + rot[n*9+5]*gy + rot[n*9+8]*gz;
            float d  = sqrtf(1e-8f + lx*lx + ly*ly + lz*lz);
            f[192 + h * 8 + p] = lx;
            f[288 + h * 8 + p] = ly;
            f[384 + h * 8 + p] = lz;
            f[480 + h * 8 + p] = d;
        }
        __syncwarp();
    }
    __syncthreads();

    float4* red = (float4*)s2d;
    #pragma unroll
    for (int hh = 0; hh < 2; hh++) {
        __syncthreads();
        #pragma unroll
        for (int q = 0; q < QB; q++) {
            u64 iv2 = pack2(sinv[q * H_ + h0 + hh]);
            u64 vx = a2[hh][q].x, vy = a2[hh][q].y;
            mul2(vx, iv2); mul2(vy, iv2);
            float2 lo = *(float2*)&vx;
            float2 hi = *(float2*)&vy;
            red[(q * 2 + mq) * 192 + hp * 32 + c4] = make_float4(lo.x, lo.y, hi.x, hi.y);
        }
        __syncthreads();
        if (mq == 0) {
            #pragma unroll
            for (int q = 0; q < QB; q++) {
                float4 a = red[(q * 2    ) * 192 + hp * 32 + c4];
                float4 b = red[(q * 2 + 1) * 192 + hp * 32 + c4];
                a.x += b.x; a.y += b.y; a.z += b.z; a.w += b.w;
                *(float4*)&g_feat[(long)(n0 + q) * NFEAT + 576 + (h0 + hh) * 128 + c4 * 4] = a;
            }
        }
    }
}

// ---------------- kernel F: output GEMM ----------------
__global__ __launch_bounds__(1024) void out_gemm_kernel(
    const float* __restrict__ B, const float* __restrict__ bias,
    float* __restrict__ C)
{
    __shared__ float As[4][16][64];
    __shared__ float Bs[4][16][36];
    int tid = threadIdx.x;
    int g = tid >> 8;
    int t = tid & 255;
    int bm = blockIdx.x * 64, bn = blockIdx.y * 32;
    int tx = t & 15, ty = t >> 4;
    int lm = t >> 2, lk4 = (t & 3) * 4;
    u64 acc[4] = {0,0,0,0};

    int kbase = g * 528;
    for (int kk0 = 0; kk0 < 528; kk0 += 16) {
        int k0 = kbase + kk0;
        float4 av = *(const float4*)&g_feat[(long)(bm + lm) * NFEAT + k0 + lk4];
        As[g][lk4+0][lm] = av.x; As[g][lk4+1][lm] = av.y;
        As[g][lk4+2][lm] = av.z; As[g][lk4+3][lm] = av.w;
        if (t < 128) {
            int bk = t >> 3, bn4 = (t & 7) * 4;
            float4 bv = *(const float4*)&B[(long)(k0 + bk) * COUT_ + bn + bn4];
            *(float4*)&Bs[g][bk][bn4] = bv;
        }
        __syncthreads();
        #pragma unroll
        for (int kk = 0; kk < 16; kk++) {
            float4 a4 = *(const float4*)&As[g][kk][ty * 4];
            u64 b = *(const u64*)&Bs[g][kk][tx * 2];
            fma2(acc[0], pack2(a4.x), b);
            fma2(acc[1], pack2(a4.y), b);
            fma2(acc[2], pack2(a4.z), b);
            fma2(acc[3], pack2(a4.w), b);
        }
        __syncthreads();
    }

    float* red = &As[0][0][0];
    #pragma unroll
    for (int r = 0; r < 2; r++) {
        __syncthreads();
        if (g > 0) {
            float2 p0 = *(float2*)&acc[r * 2];
            float2 p1 = *(float2*)&acc[r * 2 + 1];
            *(float4*)&red[((g - 1) * 256 + t) * 4] = make_float4(p0.x, p0.y, p1.x, p1.y);
        }
        __syncthreads();
        if (g == 0) {
            #pragma unroll
            for (int gg = 0; gg < 3; gg++) {
                float4 v = *(float4*)&red[(gg * 256 + t) * 4];
                float2 p0 = *(float2*)&acc[r * 2];
                float2 p1 = *(float2*)&acc[r * 2 + 1];
                p0.x += v.x; p0.y += v.y; p1.x += v.z; p1.y += v.w;
                *(float2*)&acc[r * 2]     = p0;
                *(float2*)&acc[r * 2 + 1] = p1;
            }
        }
    }
    if (g == 0) {
        float b0 = bias[bn + tx * 2], b1 = bias[bn + tx * 2 + 1];
        #pragma unroll
        for (int i = 0; i < 4; i++) {
            float2 v = *(float2*)&acc[i];
            v.x += b0; v.y += b1;
            *(float2*)&C[(long)(bm + ty * 4 + i) * COUT_ + bn + tx * 2] = v;
        }
    }
}

// ---------------- launch ----------------
extern "C" void kernel_launch(void* const* d_in, const int* in_sizes, int n_in,
                              void* d_out, int out_size)
{
    const float* inputs_1d = (const float*)d_in[0];
    const float* inputs_2d = (const float*)d_in[1];
    const float* mask      = (const float*)d_in[2];
    const float* rot       = (const float*)d_in[3];
    const float* trans     = (const float*)d_in[4];
    const float* wq        = (const float*)d_in[5];
    const float* bq        = (const float*)d_in[6];
    const float* wkv       = (const float*)d_in[7];
    const float* bkv       = (const float*)d_in[8];
    const float* wqp       = (const float*)d_in[9];
    const float* bqp       = (const float*)d_in[10];
    const float* wkvp      = (const float*)d_in[11];
    const float* bkvp      = (const float*)d_in[12];
    const float* w2d       = (const float*)d_in[13];
    const float* b2d       = (const float*)d_in[14];
    const float* tpw       = (const float*)d_in[15];
    const float* wout      = (const float*)d_in[16];
    const float* bout      = (const float*)d_in[17];
    float* out = (float*)d_out;

    proj_gemm_kernel<<<dim3(16, 18), 256>>>(inputs_1d, wq, bq, wkv, bkv,
                                            wqp, bqp, wkvp, bkvp);
    transform_kernel<<<N_, 192>>>(rot, trans, tpw);

    int smemC = (128 * PITCH + H_ * C2_) * (int)sizeof(float);
    cudaFuncSetAttribute(a2d_kernel, cudaFuncAttributeMaxDynamicSharedMemorySize, smemC);
    a2d_kernel<<<dim3(8, N_), 128, smemC>>>(inputs_2d, w2d, b2d);

    qk_kernel<<<dim3(16, 16, 12), 256>>>(mask);
    stats_kernel<<<(N_ * H_) / 8, 256>>>();

    int smemE = (QB * TM * PITCH + QB * H_ * 64 + QB * H_) * (int)sizeof(float);
    cudaFuncSetAttribute(attn_kernel, cudaFuncAttributeMaxDynamicSharedMemorySize, smemE);
    attn_kernel<<<N_ / QB, 384, smemE>>>(inputs_2d, rot, trans);

    out_gemm_kernel<<<dim3(16, 12), 1024>>>(wout, bout, out);
}